// round 7
// baseline (speedup 1.0000x reference)
#include <cuda_runtime.h>

#define NROWS  8192
#define DCOLS  4096
#define MARGINF 5.0f
#define FTHREADS 1024
#define MAXLIST 4096

// Scratch (recomputed fully each run; no cross-replay state)
__device__ float g_d[NROWS];

// One block per row: d[i] = sqrt(sum_j (recon-x)^2) + 0.001
__global__ __launch_bounds__(256) void dist_kernel(
    const float* __restrict__ recon, const float* __restrict__ x)
{
    const int row = blockIdx.x;
    const float4* r4 = reinterpret_cast<const float4*>(recon + (size_t)row * DCOLS);
    const float4* x4 = reinterpret_cast<const float4*>(x + (size_t)row * DCOLS);

    float acc = 0.0f;
    #pragma unroll 4
    for (int k = threadIdx.x; k < DCOLS / 4; k += 256) {
        float4 a = r4[k];
        float4 b = x4[k];
        float d0 = a.x - b.x;
        float d1 = a.y - b.y;
        float d2 = a.z - b.z;
        float d3 = a.w - b.w;
        acc = fmaf(d0, d0, acc);
        acc = fmaf(d1, d1, acc);
        acc = fmaf(d2, d2, acc);
        acc = fmaf(d3, d3, acc);
    }

    #pragma unroll
    for (int o = 16; o > 0; o >>= 1)
        acc += __shfl_xor_sync(0xFFFFFFFFu, acc, o);

    __shared__ float ws[8];
    if ((threadIdx.x & 31) == 0) ws[threadIdx.x >> 5] = acc;
    __syncthreads();
    if (threadIdx.x == 0) {
        float s = 0.0f;
        #pragma unroll
        for (int w = 0; w < 8; w++) s += ws[w];
        g_d[row] = sqrtf(s) + 0.001f;
    }
}

// Exact pair loss via linear decomposition + outlier correction.
//   Sum max(0, d_i - d_j + M)  over (i pos, j neg)
// = [Nn*Sp - Np*Sn + M*Np*Nn]  +  Sum max(0, d_j - d_i - M)
// The correction is nonzero only when d_j > d_i + M: gather
// pos with d_i < max_neg - M and neg with d_j > min_pos + M
// (expected O(1) elements each for this data) and brute-force exactly.
__global__ __launch_bounds__(FTHREADS) void final_kernel(
    const int* __restrict__ targets, float* __restrict__ out)
{
    __shared__ double redSp[32], redSn[32];
    __shared__ float  redMn[32], redMx[32];
    __shared__ int    redNp[32];
    __shared__ float  s_minpos, s_maxneg;
    __shared__ int    s_np;
    __shared__ float  posList[MAXLIST], negList[MAXLIST];
    __shared__ int    s_npl, s_nnl;
    __shared__ double redC[32];

    const int tid  = threadIdx.x;
    const int lane = tid & 31;
    const int wid  = tid >> 5;

    if (tid == 0) { s_npl = 0; s_nnl = 0; }

    // ---- Pass 1: sums, counts, min_pos, max_neg ----
    double sp = 0.0, sn = 0.0;
    float  mnp = 1.0e30f, mxn = -1.0e30f;
    int np = 0;
    #pragma unroll
    for (int k = tid; k < NROWS; k += FTHREADS) {
        int   t  = targets[k];
        float dv = g_d[k];
        if (t == 1) {
            sp += (double)dv;
            mnp = fminf(mnp, dv);
            np++;
        } else {
            sn += (double)dv;
            mxn = fmaxf(mxn, dv);
        }
    }
    #pragma unroll
    for (int o = 16; o > 0; o >>= 1) {
        sp  += __shfl_xor_sync(0xFFFFFFFFu, sp, o);
        sn  += __shfl_xor_sync(0xFFFFFFFFu, sn, o);
        mnp  = fminf(mnp, __shfl_xor_sync(0xFFFFFFFFu, mnp, o));
        mxn  = fmaxf(mxn, __shfl_xor_sync(0xFFFFFFFFu, mxn, o));
        np  += __shfl_xor_sync(0xFFFFFFFFu, np, o);
    }
    if (lane == 0) {
        redSp[wid] = sp; redSn[wid] = sn;
        redMn[wid] = mnp; redMx[wid] = mxn; redNp[wid] = np;
    }
    __syncthreads();
    if (tid < 32) {
        sp = redSp[tid]; sn = redSn[tid];
        mnp = redMn[tid]; mxn = redMx[tid]; np = redNp[tid];
        #pragma unroll
        for (int o = 16; o > 0; o >>= 1) {
            sp  += __shfl_xor_sync(0xFFFFFFFFu, sp, o);
            sn  += __shfl_xor_sync(0xFFFFFFFFu, sn, o);
            mnp  = fminf(mnp, __shfl_xor_sync(0xFFFFFFFFu, mnp, o));
            mxn  = fmaxf(mxn, __shfl_xor_sync(0xFFFFFFFFu, mxn, o));
            np  += __shfl_xor_sync(0xFFFFFFFFu, np, o);
        }
        if (tid == 0) {
            redSp[0] = sp; redSn[0] = sn;
            s_minpos = mnp; s_maxneg = mxn; s_np = np;
        }
    }
    __syncthreads();

    const float thrP = s_maxneg - MARGINF;  // pos matter if d_i < thrP
    const float thrN = s_minpos + MARGINF;  // neg matter if d_j > thrN

    // ---- Pass 2: gather outlier candidates (expected O(1) each) ----
    for (int k = tid; k < NROWS; k += FTHREADS) {
        int   t  = targets[k];
        float dv = g_d[k];
        if (t == 1) {
            if (dv < thrP) {
                int idx = atomicAdd(&s_npl, 1);
                if (idx < MAXLIST) posList[idx] = dv;
            }
        } else {
            if (dv > thrN) {
                int idx = atomicAdd(&s_nnl, 1);
                if (idx < MAXLIST) negList[idx] = dv;
            }
        }
    }
    __syncthreads();

    const int npl = min(s_npl, MAXLIST);
    const int nnl = min(s_nnl, MAXLIST);

    // ---- Correction: exact hinge overflow over the tiny cross product ----
    double corr = 0.0;
    for (long long e = tid; e < (long long)npl * nnl; e += FTHREADS) {
        int ip = (int)(e % npl);
        int jn = (int)(e / npl);
        float v = negList[jn] - posList[ip] - MARGINF;
        if (v > 0.0f) corr += (double)v;
    }
    #pragma unroll
    for (int o = 16; o > 0; o >>= 1)
        corr += __shfl_xor_sync(0xFFFFFFFFu, corr, o);
    if (lane == 0) redC[wid] = corr;
    __syncthreads();

    if (tid == 0) {
        double c = 0.0;
        #pragma unroll
        for (int w = 0; w < 32; w++) c += redC[w];
        double Sp = redSp[0], Sn = redSn[0];
        double Np = (double)s_np;
        double Nn = (double)(NROWS - s_np);
        double linear = Nn * Sp - Np * Sn + (double)MARGINF * Np * Nn;
        out[0] = (float)((linear + c) / (Np * Nn));
    }
}

extern "C" void kernel_launch(void* const* d_in, const int* in_sizes, int n_in,
                              void* d_out, int out_size)
{
    const float* recon   = (const float*)d_in[0];
    const float* x       = (const float*)d_in[1];
    const int*   targets = (const int*)d_in[2];
    float* out = (float*)d_out;

    dist_kernel<<<NROWS, 256>>>(recon, x);
    final_kernel<<<1, FTHREADS>>>(targets, out);
}